// round 1
// baseline (speedup 1.0000x reference)
#include <cuda_runtime.h>
#include <math.h>

#define BQ   32
#define TT   128
#define EE   256
#define HH   512
#define ENCC 512
#define VV   10000
#define G4   2048          // 4*H
#define XW   1280          // E + H + ENC

// ------------------------------------------------------------------
// scratch (static device globals; no allocations allowed)
// ------------------------------------------------------------------
__device__ float g_o[BQ * HH];                    // o = tv@Wo^T+b     (64 KB)
__device__ float g_c0[BQ * HH];                   // c0                (64 KB)
__device__ float g_base[BQ * G4];                 // time-invariant gate part
__device__ float g_G[TT * BQ * G4];               // per-step gate input (32 MB)
__device__ float g_hs[(TT + 1) * BQ * HH];        // slot0=h0, slot t+1 = h after step t
__device__ unsigned g_bar_count;                  // grid barrier
__device__ unsigned g_bar_gen;

// ------------------------------------------------------------------
// kernel 1: o, h0, c0   (warp per output, shuffle reduce)
// ------------------------------------------------------------------
__global__ void k_init(const float* __restrict__ tv,
                       const float* __restrict__ Wo, const float* __restrict__ bo,
                       const float* __restrict__ Wh, const float* __restrict__ bh,
                       const float* __restrict__ Wc, const float* __restrict__ bc)
{
    int warp = (blockIdx.x * blockDim.x + threadIdx.x) >> 5;
    int lane = threadIdx.x & 31;
    if (warp >= 3 * BQ * HH) return;
    int m   = warp / (BQ * HH);
    int rem = warp % (BQ * HH);
    int b = rem / HH, j = rem % HH;
    const float* W    = (m == 0) ? Wo : (m == 1) ? Wh : Wc;
    const float* bias = (m == 0) ? bo : (m == 1) ? bh : bc;
    const float* x = tv + b * ENCC;
    const float* w = W  + j * ENCC;
    float s = 0.f;
    for (int k = lane; k < ENCC; k += 32) s += x[k] * w[k];
    #pragma unroll
    for (int o = 16; o; o >>= 1) s += __shfl_xor_sync(0xffffffffu, s, o);
    if (lane == 0) {
        float v = s + bias[j];
        if (m == 0)      g_o[b * HH + j]  = v;
        else if (m == 1) g_hs[b * HH + j] = v;   // slot 0 = h0
        else             g_c0[b * HH + j] = v;
    }
}

// ------------------------------------------------------------------
// kernel 2: gates_base[b][n] = b_ih+b_hh + o@Wih[:,E:E+H]^T + tv@Wih[:,E+H:]^T
// ------------------------------------------------------------------
__global__ void k_base(const float* __restrict__ tv,
                       const float* __restrict__ W_ih,
                       const float* __restrict__ b_ih,
                       const float* __restrict__ b_hh)
{
    int warp = (blockIdx.x * blockDim.x + threadIdx.x) >> 5;
    int lane = threadIdx.x & 31;
    if (warp >= BQ * G4) return;
    int b = warp / G4, n = warp % G4;
    const float* w = W_ih + (size_t)n * XW + EE;        // columns E..1279
    float s = 0.f;
    for (int k = lane; k < HH + ENCC; k += 32) {
        float x = (k < HH) ? g_o[b * HH + k] : tv[b * ENCC + (k - HH)];
        s += x * w[k];
    }
    #pragma unroll
    for (int o = 16; o; o >>= 1) s += __shfl_xor_sync(0xffffffffu, s, o);
    if (lane == 0) g_base[b * G4 + n] = s + b_ih[n] + b_hh[n];
}

// ------------------------------------------------------------------
// kernel 3: G[t][b][n] = emb[token(t-1)] @ W_ih[:, :E]^T + gates_base
// tiled GEMM M=4096 (row = t*32+b), N=2048, K=256
// ------------------------------------------------------------------
#define GM 64
#define GN 64
#define GK 16
__global__ void __launch_bounds__(256) k_G(const float* __restrict__ emb,
                                           const int*   __restrict__ texts,
                                           const int*   __restrict__ startp,
                                           const float* __restrict__ W_ih)
{
    __shared__ float As[GK][GM + 4];
    __shared__ float Bs[GK][GN + 4];
    __shared__ int   rowoff[GM];
    int tid = threadIdx.x;
    int nt = blockIdx.x, mt = blockIdx.y;

    if (tid < GM) {
        int r = mt * GM + tid;
        int t = r >> 5, b = r & 31;
        int tok = (t == 0) ? startp[0] : texts[b * TT + t - 1];
        rowoff[tid] = tok * EE;
    }
    __syncthreads();

    int tm = tid >> 4, tn = tid & 15;
    int lrow = tid >> 2;            // loader row 0..63
    int lk   = (tid & 3) * 4;       // loader k offset 0,4,8,12
    float acc[4][4] = {};

    for (int k0 = 0; k0 < EE; k0 += GK) {
        float4 av = *(const float4*)(emb + rowoff[lrow] + k0 + lk);
        float4 bv = *(const float4*)(W_ih + (size_t)(nt * GN + lrow) * XW + k0 + lk);
        __syncthreads();
        As[lk + 0][lrow] = av.x; As[lk + 1][lrow] = av.y;
        As[lk + 2][lrow] = av.z; As[lk + 3][lrow] = av.w;
        Bs[lk + 0][lrow] = bv.x; Bs[lk + 1][lrow] = bv.y;
        Bs[lk + 2][lrow] = bv.z; Bs[lk + 3][lrow] = bv.w;
        __syncthreads();
        #pragma unroll
        for (int kk = 0; kk < GK; kk++) {
            float4 a4 = *(const float4*)&As[kk][tm * 4];
            float4 b4 = *(const float4*)&Bs[kk][tn * 4];
            float ar[4] = {a4.x, a4.y, a4.z, a4.w};
            float br[4] = {b4.x, b4.y, b4.z, b4.w};
            #pragma unroll
            for (int i = 0; i < 4; i++)
                #pragma unroll
                for (int j = 0; j < 4; j++)
                    acc[i][j] = fmaf(ar[i], br[j], acc[i][j]);
        }
    }
    #pragma unroll
    for (int i = 0; i < 4; i++) {
        int r = mt * GM + tm * 4 + i;
        int ncol = nt * GN + tn * 4;
        float4 bs = *(const float4*)&g_base[(r & 31) * G4 + ncol];
        float4 v;
        v.x = acc[i][0] + bs.x; v.y = acc[i][1] + bs.y;
        v.z = acc[i][2] + bs.z; v.w = acc[i][3] + bs.w;
        *(float4*)&g_G[(size_t)r * G4 + ncol] = v;
    }
}

// ------------------------------------------------------------------
// kernel 4: sequential LSTM. Persistent, 128 CTAs, grid barrier per step.
// CTA p owns h-indices [4p,4p+4) => 16 gate rows (i,f,g,o) kept in SMEM.
// ------------------------------------------------------------------
__global__ void __launch_bounds__(256, 1) k_lstm(const float* __restrict__ W_hh)
{
    extern __shared__ float smem[];
    float*  sW    = smem;                         // 16*512  floats (32 KB)
    float4* sW4   = (float4*)sW;
    float*  sH    = smem + 16 * 512;              // 64*32 float4 (32 KB)
    float4* sH4   = (float4*)sH;
    float*  sGate = sH + 64 * 32 * 4;             // 16*32
    float*  sC    = sGate + 16 * 32;              // 4*32
    __shared__ unsigned sGen;

    int tid = threadIdx.x;
    int p   = blockIdx.x;
    int b   = tid & 31;        // lane = batch
    int rr  = tid >> 5;        // 0..7
    int lr0 = rr, lr1 = rr + 8;
    // global gate row for local row lr = gate*4+q : n = gate*512 + 4p + q
    int n0 = (lr0 >> 2) * HH + p * 4 + (lr0 & 3);
    int n1 = (lr1 >> 2) * HH + p * 4 + (lr1 & 3);

    // load W_hh rows for our 16 gate rows
    for (int idx = tid; idx < 16 * 128; idx += 256) {
        int lr = idx >> 7, k4 = idx & 127;
        int n  = (lr >> 2) * HH + p * 4 + (lr & 3);
        sW4[lr * 128 + k4] = *(const float4*)(W_hh + (size_t)n * HH + k4 * 4);
    }
    // load c0 slice
    if (tid < 128) {
        int q = tid >> 5, b2 = tid & 31;
        sC[q * 32 + b2] = g_c0[b2 * HH + p * 4 + q];
    }
    if (tid == 0) sGen = g_bar_gen;   // safe: no increment until every CTA arrives
    __syncthreads();
    unsigned base_gen = sGen;

    for (int t = 0; t < TT; t++) {
        const float* hprev = g_hs + (size_t)t * (BQ * HH);
        float4 accA = {0, 0, 0, 0}, accB = {0, 0, 0, 0};
        #pragma unroll
        for (int half = 0; half < 2; half++) {
            // stage h (transposed-by-4) into SMEM: [k4][b] float4
            for (int idx = tid; idx < 64 * 32; idx += 256) {
                int k4 = idx >> 5, bb = idx & 31;
                sH4[idx] = __ldcg((const float4*)(hprev + bb * HH + half * 256 + k4 * 4));
            }
            __syncthreads();
            const float4* wA = sW4 + lr0 * 128 + half * 64;
            const float4* wB = sW4 + lr1 * 128 + half * 64;
            #pragma unroll 4
            for (int k4 = 0; k4 < 64; k4++) {
                float4 h4 = sH4[k4 * 32 + b];
                float4 a  = wA[k4];
                float4 c  = wB[k4];
                accA.x = fmaf(h4.x, a.x, accA.x);
                accA.y = fmaf(h4.y, a.y, accA.y);
                accA.z = fmaf(h4.z, a.z, accA.z);
                accA.w = fmaf(h4.w, a.w, accA.w);
                accB.x = fmaf(h4.x, c.x, accB.x);
                accB.y = fmaf(h4.y, c.y, accB.y);
                accB.z = fmaf(h4.z, c.z, accB.z);
                accB.w = fmaf(h4.w, c.w, accB.w);
            }
            __syncthreads();
        }
        float gA = (accA.x + accA.y) + (accA.z + accA.w)
                 + g_G[(size_t)(t * BQ + b) * G4 + n0];
        float gB = (accB.x + accB.y) + (accB.z + accB.w)
                 + g_G[(size_t)(t * BQ + b) * G4 + n1];
        sGate[lr0 * 32 + b] = gA;
        sGate[lr1 * 32 + b] = gB;
        __syncthreads();
        if (tid < 128) {
            int q = tid >> 5, b2 = tid & 31;
            float ig = sGate[(q     ) * 32 + b2];
            float fg = sGate[(4  + q) * 32 + b2];
            float gg = sGate[(8  + q) * 32 + b2];
            float og = sGate[(12 + q) * 32 + b2];
            float iS = 1.f / (1.f + expf(-ig));
            float fS = 1.f / (1.f + expf(-fg));
            float gT = tanhf(gg);
            float oS = 1.f / (1.f + expf(-og));
            float c  = fS * sC[q * 32 + b2] + iS * gT;
            sC[q * 32 + b2] = c;
            float h = oS * tanhf(c);
            g_hs[(size_t)(t + 1) * (BQ * HH) + b2 * HH + p * 4 + q] = h;
        }
        // ---- grid barrier ----
        __threadfence();
        __syncthreads();
        if (tid == 0) {
            unsigned target = base_gen + (unsigned)(t + 1);
            unsigned arr = atomicAdd(&g_bar_count, 1u);
            if (arr == 127u) {
                g_bar_count = 0u;
                __threadfence();
                atomicExch(&g_bar_gen, target);
            } else {
                volatile unsigned* vg = &g_bar_gen;
                while (*vg < target) { }
            }
            __threadfence();
        }
        __syncthreads();
    }
}

// ------------------------------------------------------------------
// kernel 5: logits = hs[4096,512] @ Wv^T[512,10000] + b, scattered to [b,t,v]
// 128x128x16 tiled SGEMM, 8x8 microtile
// ------------------------------------------------------------------
#define LM 128
#define LN 128
#define LK 16
__global__ void __launch_bounds__(256) k_logits(const float* __restrict__ Wv,
                                                const float* __restrict__ bv,
                                                float* __restrict__ out)
{
    __shared__ float As[LK][LM + 4];
    __shared__ float Bs[LK][LN + 4];
    int tid = threadIdx.x;
    int nt = blockIdx.x, mt = blockIdx.y;
    const float* A = g_hs + BQ * HH;   // skip slot 0 (h0): row r -> h after step r/32

    int tm = tid >> 4, tn = tid & 15;
    float acc[8][8] = {};

    for (int k0 = 0; k0 < HH; k0 += LK) {
        float4 av[2], bb[2];
        #pragma unroll
        for (int i = 0; i < 2; i++) {
            int idx = tid + i * 256;
            int row = idx >> 2, kq = (idx & 3) * 4;
            av[i] = *(const float4*)(A + (size_t)(mt * LM + row) * HH + k0 + kq);
            int n = nt * LN + row;
            if (n < VV) bb[i] = *(const float4*)(Wv + (size_t)n * HH + k0 + kq);
            else        bb[i] = make_float4(0.f, 0.f, 0.f, 0.f);
        }
        __syncthreads();
        #pragma unroll
        for (int i = 0; i < 2; i++) {
            int idx = tid + i * 256;
            int row = idx >> 2, kq = (idx & 3) * 4;
            As[kq + 0][row] = av[i].x; As[kq + 1][row] = av[i].y;
            As[kq + 2][row] = av[i].z; As[kq + 3][row] = av[i].w;
            Bs[kq + 0][row] = bb[i].x; Bs[kq + 1][row] = bb[i].y;
            Bs[kq + 2][row] = bb[i].z; Bs[kq + 3][row] = bb[i].w;
        }
        __syncthreads();
        #pragma unroll
        for (int kk = 0; kk < LK; kk++) {
            float4 a0 = *(const float4*)&As[kk][tm * 4];
            float4 a1 = *(const float4*)&As[kk][tm * 4 + 64];
            float4 b0 = *(const float4*)&Bs[kk][tn * 4];
            float4 b1 = *(const float4*)&Bs[kk][tn * 4 + 64];
            float ar[8] = {a0.x, a0.y, a0.z, a0.w, a1.x, a1.y, a1.z, a1.w};
            float br[8] = {b0.x, b0.y, b0.z, b0.w, b1.x, b1.y, b1.z, b1.w};
            #pragma unroll
            for (int i = 0; i < 8; i++)
                #pragma unroll
                for (int j = 0; j < 8; j++)
                    acc[i][j] = fmaf(ar[i], br[j], acc[i][j]);
        }
    }
    // epilogue: row r = t*32+b  ->  out[b][t][:]
    #pragma unroll
    for (int ii = 0; ii < 8; ii++) {
        int rlocal = (ii < 4) ? (tm * 4 + ii) : (64 + tm * 4 + ii - 4);
        int r = mt * LM + rlocal;
        int bI = r & 31, tI = r >> 5;
        float* orow = out + (size_t)bI * TT * VV + (size_t)tI * VV;
        #pragma unroll
        for (int j2 = 0; j2 < 2; j2++) {
            int col = nt * LN + tn * 4 + j2 * 64;
            if (col < VV) {
                float4 bias4 = *(const float4*)(bv + col);
                float4 v;
                v.x = acc[ii][j2 * 4 + 0] + bias4.x;
                v.y = acc[ii][j2 * 4 + 1] + bias4.y;
                v.z = acc[ii][j2 * 4 + 2] + bias4.z;
                v.w = acc[ii][j2 * 4 + 3] + bias4.w;
                *(float4*)(orow + col) = v;
            }
        }
    }
}

// ------------------------------------------------------------------
extern "C" void kernel_launch(void* const* d_in, const int* in_sizes, int n_in,
                              void* d_out, int out_size)
{
    const float* tv    = (const float*)d_in[0];
    const int*   texts = (const int*)  d_in[1];
    /* d_in[2] = lengths, unused */
    const int*   start = (const int*)  d_in[3];
    const float* emb   = (const float*)d_in[4];
    const float* W_ih  = (const float*)d_in[5];
    const float* b_ih  = (const float*)d_in[6];
    const float* W_hh  = (const float*)d_in[7];
    const float* b_hh  = (const float*)d_in[8];
    const float* Wo_w  = (const float*)d_in[9];
    const float* Wo_b  = (const float*)d_in[10];
    const float* Wh_w  = (const float*)d_in[11];
    const float* Wh_b  = (const float*)d_in[12];
    const float* Wc_w  = (const float*)d_in[13];
    const float* Wc_b  = (const float*)d_in[14];
    const float* Wv_w  = (const float*)d_in[15];
    const float* Wv_b  = (const float*)d_in[16];
    float* out = (float*)d_out;

    const int lstm_smem = (16 * 512 + 64 * 32 * 4 + 16 * 32 + 4 * 32) * 4; // 68096 B
    cudaFuncSetAttribute(k_lstm, cudaFuncAttributeMaxDynamicSharedMemorySize, 69632);

    k_init<<<6144, 256>>>(tv, Wo_w, Wo_b, Wh_w, Wh_b, Wc_w, Wc_b);
    k_base<<<8192, 256>>>(tv, W_ih, b_ih, b_hh);
    k_G<<<dim3(G4 / GN, (TT * BQ) / GM), 256>>>(emb, texts, start, W_ih);
    k_lstm<<<128, 256, lstm_smem>>>(W_hh);
    k_logits<<<dim3((VV + LN - 1) / LN, (TT * BQ) / LM), 256>>>(Wv_w, Wv_b, out);
}

// round 3
// speedup vs baseline: 1.1737x; 1.1737x over previous
#include <cuda_runtime.h>
#include <cuda_bf16.h>
#include <cstdint>
#include <math.h>

#define BQ   32
#define TT   128
#define EE   256
#define HH   512
#define ENCC 512
#define VV   10000
#define G4   2048          // 4*H
#define XW   1280          // E + H + ENC
#define VPAD 10112         // 79 * 128

// ------------------------------------------------------------------
// scratch (static device globals; no allocations allowed)
// ------------------------------------------------------------------
__device__ float g_o[BQ * HH];
__device__ float g_c0[BQ * HH];
__device__ float g_base[BQ * G4];
__device__ float g_G[TT * BQ * G4];               // per-step gate input (32 MB)
__device__ float g_hs[(TT + 1) * BQ * HH];        // slot0=h0, slot t+1 = h after step t
__device__ unsigned g_bar_count;
__device__ unsigned g_bar_gen;

// bf16 hi/lo split operands for the tensor-core logits GEMM
__device__ __nv_bfloat16 g_Ahi[TT * BQ * HH];     // 4 MB
__device__ __nv_bfloat16 g_Alo[TT * BQ * HH];
__device__ __nv_bfloat16 g_Bhi[VPAD * HH];        // 10 MB (zero-padded rows)
__device__ __nv_bfloat16 g_Blo[VPAD * HH];

// ------------------------------------------------------------------
// kernel 1: o, h0, c0   (warp per output, shuffle reduce)
// ------------------------------------------------------------------
__global__ void k_init(const float* __restrict__ tv,
                       const float* __restrict__ Wo, const float* __restrict__ bo,
                       const float* __restrict__ Wh, const float* __restrict__ bh,
                       const float* __restrict__ Wc, const float* __restrict__ bc)
{
    int warp = (blockIdx.x * blockDim.x + threadIdx.x) >> 5;
    int lane = threadIdx.x & 31;
    if (warp >= 3 * BQ * HH) return;
    int m   = warp / (BQ * HH);
    int rem = warp % (BQ * HH);
    int b = rem / HH, j = rem % HH;
    const float* W    = (m == 0) ? Wo : (m == 1) ? Wh : Wc;
    const float* bias = (m == 0) ? bo : (m == 1) ? bh : bc;
    const float* x = tv + b * ENCC;
    const float* w = W  + j * ENCC;
    float s = 0.f;
    for (int k = lane; k < ENCC; k += 32) s += x[k] * w[k];
    #pragma unroll
    for (int o = 16; o; o >>= 1) s += __shfl_xor_sync(0xffffffffu, s, o);
    if (lane == 0) {
        float v = s + bias[j];
        if (m == 0)      g_o[b * HH + j]  = v;
        else if (m == 1) g_hs[b * HH + j] = v;   // slot 0 = h0
        else             g_c0[b * HH + j] = v;
    }
}

// ------------------------------------------------------------------
// kernel 2: gates_base
// ------------------------------------------------------------------
__global__ void k_base(const float* __restrict__ tv,
                       const float* __restrict__ W_ih,
                       const float* __restrict__ b_ih,
                       const float* __restrict__ b_hh)
{
    int warp = (blockIdx.x * blockDim.x + threadIdx.x) >> 5;
    int lane = threadIdx.x & 31;
    if (warp >= BQ * G4) return;
    int b = warp / G4, n = warp % G4;
    const float* w = W_ih + (size_t)n * XW + EE;
    float s = 0.f;
    for (int k = lane; k < HH + ENCC; k += 32) {
        float x = (k < HH) ? g_o[b * HH + k] : tv[b * ENCC + (k - HH)];
        s += x * w[k];
    }
    #pragma unroll
    for (int o = 16; o; o >>= 1) s += __shfl_xor_sync(0xffffffffu, s, o);
    if (lane == 0) g_base[b * G4 + n] = s + b_ih[n] + b_hh[n];
}

// ------------------------------------------------------------------
// kernel 3: G[t][b][n] = emb[token(t-1)] @ W_ih[:, :E]^T + gates_base
// ------------------------------------------------------------------
#define GM 64
#define GN 64
#define GK 16
__global__ void __launch_bounds__(256) k_G(const float* __restrict__ emb,
                                           const int*   __restrict__ texts,
                                           const int*   __restrict__ startp,
                                           const float* __restrict__ W_ih)
{
    __shared__ float As[GK][GM + 4];
    __shared__ float Bs[GK][GN + 4];
    __shared__ int   rowoff[GM];
    int tid = threadIdx.x;
    int nt = blockIdx.x, mt = blockIdx.y;

    if (tid < GM) {
        int r = mt * GM + tid;
        int t = r >> 5, b = r & 31;
        int tok = (t == 0) ? startp[0] : texts[b * TT + t - 1];
        rowoff[tid] = tok * EE;
    }
    __syncthreads();

    int tm = tid >> 4, tn = tid & 15;
    int lrow = tid >> 2;
    int lk   = (tid & 3) * 4;
    float acc[4][4] = {};

    for (int k0 = 0; k0 < EE; k0 += GK) {
        float4 av = *(const float4*)(emb + rowoff[lrow] + k0 + lk);
        float4 bv = *(const float4*)(W_ih + (size_t)(nt * GN + lrow) * XW + k0 + lk);
        __syncthreads();
        As[lk + 0][lrow] = av.x; As[lk + 1][lrow] = av.y;
        As[lk + 2][lrow] = av.z; As[lk + 3][lrow] = av.w;
        Bs[lk + 0][lrow] = bv.x; Bs[lk + 1][lrow] = bv.y;
        Bs[lk + 2][lrow] = bv.z; Bs[lk + 3][lrow] = bv.w;
        __syncthreads();
        #pragma unroll
        for (int kk = 0; kk < GK; kk++) {
            float4 a4 = *(const float4*)&As[kk][tm * 4];
            float4 b4 = *(const float4*)&Bs[kk][tn * 4];
            float ar[4] = {a4.x, a4.y, a4.z, a4.w};
            float br[4] = {b4.x, b4.y, b4.z, b4.w};
            #pragma unroll
            for (int i = 0; i < 4; i++)
                #pragma unroll
                for (int j = 0; j < 4; j++)
                    acc[i][j] = fmaf(ar[i], br[j], acc[i][j]);
        }
    }
    #pragma unroll
    for (int i = 0; i < 4; i++) {
        int r = mt * GM + tm * 4 + i;
        int ncol = nt * GN + tn * 4;
        float4 bs = *(const float4*)&g_base[(r & 31) * G4 + ncol];
        float4 v;
        v.x = acc[i][0] + bs.x; v.y = acc[i][1] + bs.y;
        v.z = acc[i][2] + bs.z; v.w = acc[i][3] + bs.w;
        *(float4*)&g_G[(size_t)r * G4 + ncol] = v;
    }
}

// ------------------------------------------------------------------
// kernel 4: sequential LSTM (persistent, 128 CTAs, grid barrier per step)
// ------------------------------------------------------------------
__global__ void __launch_bounds__(256, 1) k_lstm(const float* __restrict__ W_hh)
{
    extern __shared__ float smem[];
    float*  sW    = smem;
    float4* sW4   = (float4*)sW;
    float*  sH    = smem + 16 * 512;
    float4* sH4   = (float4*)sH;
    float*  sGate = sH + 64 * 32 * 4;
    float*  sC    = sGate + 16 * 32;
    __shared__ unsigned sGen;

    int tid = threadIdx.x;
    int p   = blockIdx.x;
    int b   = tid & 31;
    int rr  = tid >> 5;
    int lr0 = rr, lr1 = rr + 8;
    int n0 = (lr0 >> 2) * HH + p * 4 + (lr0 & 3);
    int n1 = (lr1 >> 2) * HH + p * 4 + (lr1 & 3);

    for (int idx = tid; idx < 16 * 128; idx += 256) {
        int lr = idx >> 7, k4 = idx & 127;
        int n  = (lr >> 2) * HH + p * 4 + (lr & 3);
        sW4[lr * 128 + k4] = *(const float4*)(W_hh + (size_t)n * HH + k4 * 4);
    }
    if (tid < 128) {
        int q = tid >> 5, b2 = tid & 31;
        sC[q * 32 + b2] = g_c0[b2 * HH + p * 4 + q];
    }
    if (tid == 0) sGen = g_bar_gen;
    __syncthreads();
    unsigned base_gen = sGen;

    for (int t = 0; t < TT; t++) {
        const float* hprev = g_hs + (size_t)t * (BQ * HH);
        float4 accA = {0, 0, 0, 0}, accB = {0, 0, 0, 0};
        #pragma unroll
        for (int half = 0; half < 2; half++) {
            for (int idx = tid; idx < 64 * 32; idx += 256) {
                int k4 = idx >> 5, bb = idx & 31;
                sH4[idx] = __ldcg((const float4*)(hprev + bb * HH + half * 256 + k4 * 4));
            }
            __syncthreads();
            const float4* wA = sW4 + lr0 * 128 + half * 64;
            const float4* wB = sW4 + lr1 * 128 + half * 64;
            #pragma unroll 4
            for (int k4 = 0; k4 < 64; k4++) {
                float4 h4 = sH4[k4 * 32 + b];
                float4 a  = wA[k4];
                float4 c  = wB[k4];
                accA.x = fmaf(h4.x, a.x, accA.x);
                accA.y = fmaf(h4.y, a.y, accA.y);
                accA.z = fmaf(h4.z, a.z, accA.z);
                accA.w = fmaf(h4.w, a.w, accA.w);
                accB.x = fmaf(h4.x, c.x, accB.x);
                accB.y = fmaf(h4.y, c.y, accB.y);
                accB.z = fmaf(h4.z, c.z, accB.z);
                accB.w = fmaf(h4.w, c.w, accB.w);
            }
            __syncthreads();
        }
        float gA = (accA.x + accA.y) + (accA.z + accA.w)
                 + g_G[(size_t)(t * BQ + b) * G4 + n0];
        float gB = (accB.x + accB.y) + (accB.z + accB.w)
                 + g_G[(size_t)(t * BQ + b) * G4 + n1];
        sGate[lr0 * 32 + b] = gA;
        sGate[lr1 * 32 + b] = gB;
        __syncthreads();
        if (tid < 128) {
            int q = tid >> 5, b2 = tid & 31;
            float ig = sGate[(q     ) * 32 + b2];
            float fg = sGate[(4  + q) * 32 + b2];
            float gg = sGate[(8  + q) * 32 + b2];
            float og = sGate[(12 + q) * 32 + b2];
            float iS = 1.f / (1.f + expf(-ig));
            float fS = 1.f / (1.f + expf(-fg));
            float gT = tanhf(gg);
            float oS = 1.f / (1.f + expf(-og));
            float c  = fS * sC[q * 32 + b2] + iS * gT;
            sC[q * 32 + b2] = c;
            float h = oS * tanhf(c);
            g_hs[(size_t)(t + 1) * (BQ * HH) + b2 * HH + p * 4 + q] = h;
        }
        __threadfence();
        __syncthreads();
        if (tid == 0) {
            unsigned target = base_gen + (unsigned)(t + 1);
            unsigned arr = atomicAdd(&g_bar_count, 1u);
            if (arr == 127u) {
                g_bar_count = 0u;
                __threadfence();
                atomicExch(&g_bar_gen, target);
            } else {
                volatile unsigned* vg = &g_bar_gen;
                while (*vg < target) { }
            }
            __threadfence();
        }
        __syncthreads();
    }
}

// ------------------------------------------------------------------
// conversion kernels: fp32 -> bf16 hi/lo split
// ------------------------------------------------------------------
__global__ void k_convA()
{
    int idx = blockIdx.x * 256 + threadIdx.x;          // TT*BQ*HH = 2097152
    float x = g_hs[BQ * HH + idx];
    __nv_bfloat16 hi = __float2bfloat16(x);
    float r = x - __bfloat162float(hi);
    g_Ahi[idx] = hi;
    g_Alo[idx] = __float2bfloat16(r);
}

__global__ void k_convB(const float* __restrict__ Wv)
{
    size_t idx = (size_t)blockIdx.x * 256 + threadIdx.x;   // VPAD*HH
    int n = (int)(idx >> 9);
    float x = (n < VV) ? Wv[idx] : 0.f;
    __nv_bfloat16 hi = __float2bfloat16(x);
    float r = x - __bfloat162float(hi);
    g_Bhi[idx] = hi;
    g_Blo[idx] = __float2bfloat16(r);
}

// ------------------------------------------------------------------
// mma / ldmatrix / cp.async helpers (reference-param style, per ptx_helpers)
// ------------------------------------------------------------------
__device__ __forceinline__ void cp_async16(uint32_t dst, const void* src)
{
    asm volatile("cp.async.cg.shared.global [%0], [%1], 16;" :: "r"(dst), "l"(src));
}
__device__ __forceinline__ void cp_commit()
{
    asm volatile("cp.async.commit_group;");
}
__device__ __forceinline__ void ldsm_x4(uint32_t& r0, uint32_t& r1,
                                        uint32_t& r2, uint32_t& r3, uint32_t addr)
{
    asm volatile("ldmatrix.sync.aligned.m8n8.x4.shared.b16 {%0,%1,%2,%3}, [%4];"
                 : "=r"(r0), "=r"(r1), "=r"(r2), "=r"(r3) : "r"(addr));
}
__device__ __forceinline__ void ldsm_x2(uint32_t& r0, uint32_t& r1, uint32_t addr)
{
    asm volatile("ldmatrix.sync.aligned.m8n8.x2.shared.b16 {%0,%1}, [%2];"
                 : "=r"(r0), "=r"(r1) : "r"(addr));
}
__device__ __forceinline__ void mma16816(float& c0, float& c1, float& c2, float& c3,
                                         uint32_t a0, uint32_t a1, uint32_t a2, uint32_t a3,
                                         uint32_t b0, uint32_t b1)
{
    asm volatile("mma.sync.aligned.m16n8k16.row.col.f32.bf16.bf16.f32 "
                 "{%0,%1,%2,%3}, {%4,%5,%6,%7}, {%8,%9}, {%0,%1,%2,%3};"
                 : "+f"(c0), "+f"(c1), "+f"(c2), "+f"(c3)
                 : "r"(a0), "r"(a1), "r"(a2), "r"(a3), "r"(b0), "r"(b1));
}

// ------------------------------------------------------------------
// kernel 5: logits via bf16 HMMA, 3-term hi/lo split (effective K = 1536)
// block tile 128x128, 8 warps (2m x 4n), warp tile 64x32, K-tile 32
// SMEM rows padded to 40 bf16 (80 B) for conflict-free ldmatrix
// ------------------------------------------------------------------
#define MMA_SMEM_BUF 20480           // A(10240) + B(10240) per buffer

__device__ __forceinline__ void logits_load_tile(
    int kt, int buf, int tid, int mtb, int ntb, uint32_t sbase)
{
    const int pass = kt >> 4;
    const int k0   = (kt & 15) * 32;
    const __nv_bfloat16* pA = (pass == 1) ? g_Alo : g_Ahi;
    const __nv_bfloat16* pB = (pass == 2) ? g_Blo : g_Bhi;
    const uint32_t abase = sbase + buf * MMA_SMEM_BUF;
    const uint32_t bbase = abase + 10240;
    #pragma unroll
    for (int i = 0; i < 2; i++) {
        int ch  = tid + i * 256;          // 0..511
        int row = ch >> 2, kc = ch & 3;
        cp_async16(abase + row * 80 + kc * 16,
                   pA + (size_t)(mtb * 128 + row) * HH + k0 + kc * 8);
        cp_async16(bbase + row * 80 + kc * 16,
                   pB + (size_t)(ntb * 128 + row) * HH + k0 + kc * 8);
    }
}

__global__ void __launch_bounds__(256) k_logits_mma(const float* __restrict__ bv,
                                                    float* __restrict__ out)
{
    __shared__ __align__(16) unsigned char smem[2 * MMA_SMEM_BUF];
    const int tid  = threadIdx.x;
    const int lane = tid & 31;
    const int warp = tid >> 5;
    const int ntb  = blockIdx.x;     // 0..78
    const int mtb  = blockIdx.y;     // 0..31

    const int wm = (warp >> 2) * 64;
    const int wn = (warp & 3) * 32;

    uint32_t sbase = (uint32_t)__cvta_generic_to_shared(smem);

    float acc[4][4][4];
    #pragma unroll
    for (int i = 0; i < 4; i++)
        #pragma unroll
        for (int j = 0; j < 4; j++) {
            acc[i][j][0] = 0.f; acc[i][j][1] = 0.f;
            acc[i][j][2] = 0.f; acc[i][j][3] = 0.f;
        }

    // ldmatrix lane address offsets (bytes within a buffer)
    const int amat  = lane >> 3;
    const uint32_t a_lane_off = (uint32_t)((wm + (amat & 1) * 8 + (lane & 7)) * 80
                                           + ((amat >> 1) * 8) * 2);
    const int blane = lane & 15;
    const uint32_t b_lane_off = (uint32_t)(10240 + (wn + (blane & 7)) * 80
                                           + ((blane >> 3) * 8) * 2);

    const int NKT = 48;                        // 3 passes * 16 k-tiles
    logits_load_tile(0, 0, tid, mtb, ntb, sbase);
    cp_commit();

    for (int kt = 0; kt < NKT; kt++) {
        if (kt + 1 < NKT) {
            logits_load_tile(kt + 1, (kt + 1) & 1, tid, mtb, ntb, sbase);
            cp_commit();
            asm volatile("cp.async.wait_group 1;");
        } else {
            asm volatile("cp.async.wait_group 0;");
        }
        __syncthreads();

        const uint32_t abase = sbase + (kt & 1) * MMA_SMEM_BUF;
        #pragma unroll
        for (int k16 = 0; k16 < 2; k16++) {
            uint32_t af[4][4];
            uint32_t bf[4][2];
            #pragma unroll
            for (int mt = 0; mt < 4; mt++) {
                uint32_t ad = abase + a_lane_off + mt * (16 * 80) + k16 * 32;
                ldsm_x4(af[mt][0], af[mt][1], af[mt][2], af[mt][3], ad);
            }
            #pragma unroll
            for (int nt = 0; nt < 4; nt++) {
                uint32_t bd = abase + b_lane_off + nt * (8 * 80) + k16 * 32;
                ldsm_x2(bf[nt][0], bf[nt][1], bd);
            }
            #pragma unroll
            for (int mt = 0; mt < 4; mt++)
                #pragma unroll
                for (int nt = 0; nt < 4; nt++)
                    mma16816(acc[mt][nt][0], acc[mt][nt][1],
                             acc[mt][nt][2], acc[mt][nt][3],
                             af[mt][0], af[mt][1], af[mt][2], af[mt][3],
                             bf[nt][0], bf[nt][1]);
        }
        __syncthreads();
    }

    // epilogue: row m = t*32+b  ->  out[b][t][col], add bias
    #pragma unroll
    for (int mt = 0; mt < 4; mt++) {
        #pragma unroll
        for (int nt = 0; nt < 4; nt++) {
            int col = ntb * 128 + wn + nt * 8 + (lane & 3) * 2;
            if (col < VV) {
                float bb0 = __ldg(bv + col);
                float bb1 = __ldg(bv + col + 1);
                int m0 = mtb * 128 + wm + mt * 16 + (lane >> 2);
                int bI = m0 & 31, tI = m0 >> 5;
                float2 v0 = { acc[mt][nt][0] + bb0, acc[mt][nt][1] + bb1 };
                *(float2*)(out + (size_t)bI * TT * VV + (size_t)tI * VV + col) = v0;
                int m1 = m0 + 8;
                bI = m1 & 31; tI = m1 >> 5;
                float2 v1 = { acc[mt][nt][2] + bb0, acc[mt][nt][3] + bb1 };
                *(float2*)(out + (size_t)bI * TT * VV + (size_t)tI * VV + col) = v1;
            }
        }
    }
}

// ------------------------------------------------------------------
extern "C" void kernel_launch(void* const* d_in, const int* in_sizes, int n_in,
                              void* d_out, int out_size)
{
    const float* tv    = (const float*)d_in[0];
    const int*   texts = (const int*)  d_in[1];
    const int*   start = (const int*)  d_in[3];
    const float* emb   = (const float*)d_in[4];
    const float* W_ih  = (const float*)d_in[5];
    const float* b_ih  = (const float*)d_in[6];
    const float* W_hh  = (const float*)d_in[7];
    const float* b_hh  = (const float*)d_in[8];
    const float* Wo_w  = (const float*)d_in[9];
    const float* Wo_b  = (const float*)d_in[10];
    const float* Wh_w  = (const float*)d_in[11];
    const float* Wh_b  = (const float*)d_in[12];
    const float* Wc_w  = (const float*)d_in[13];
    const float* Wc_b  = (const float*)d_in[14];
    const float* Wv_w  = (const float*)d_in[15];
    const float* Wv_b  = (const float*)d_in[16];
    float* out = (float*)d_out;

    const int lstm_smem = (16 * 512 + 64 * 32 * 4 + 16 * 32 + 4 * 32) * 4;
    cudaFuncSetAttribute(k_lstm, cudaFuncAttributeMaxDynamicSharedMemorySize, 69632);

    k_init<<<6144, 256>>>(tv, Wo_w, Wo_b, Wh_w, Wh_b, Wc_w, Wc_b);
    k_base<<<8192, 256>>>(tv, W_ih, b_ih, b_hh);
    k_G<<<dim3(G4 / GN, (TT * BQ) / GM), 256>>>(emb, texts, start, W_ih);
    k_convB<<<(VPAD * HH) / 256, 256>>>(Wv_w);
    k_lstm<<<128, 256, lstm_smem>>>(W_hh);
    k_convA<<<(TT * BQ * HH) / 256, 256>>>();
    k_logits_mma<<<dim3(VPAD / 128, (TT * BQ) / 128), 256>>>(Wv_b, out);
}